// round 8
// baseline (speedup 1.0000x reference)
#include <cuda_runtime.h>
#include <math.h>

// Fixed problem shapes
#define BB 16
#define HH 256
#define WW 256
#define SS 24
#define PS (HH * WW)             // per-channel plane stride
#define NPIX (BB * HH * WW)      // 1,048,576
#define NQUAD 1024               // work units: 4 rows each
#define NSM 152                  // GB300 SM count
#define GRID (4 * NSM)           // 608 persistent blocks, exactly 4 resident/SM
#define EPSF 1e-6f
#define WGRAD 0.05f

typedef unsigned long long ull;

__device__ float2 g_partials[NQUAD];
__device__ unsigned int g_work = 0;
__device__ unsigned int g_done = 0;

// ---------- packed f32x2 + MUFU helpers ----------
__device__ __forceinline__ ull pack2(float lo, float hi) {
    ull r; asm("mov.b64 %0, {%1, %2};" : "=l"(r) : "f"(lo), "f"(hi)); return r;
}
__device__ __forceinline__ void unpack2(ull v, float& lo, float& hi) {
    asm("mov.b64 {%0, %1}, %2;" : "=f"(lo), "=f"(hi) : "l"(v));
}
__device__ __forceinline__ ull fma2(ull a, ull b, ull c) {
    ull r; asm("fma.rn.f32x2 %0, %1, %2, %3;" : "=l"(r) : "l"(a), "l"(b), "l"(c)); return r;
}
__device__ __forceinline__ ull mul2(ull a, ull b) {
    ull r; asm("mul.rn.f32x2 %0, %1, %2;" : "=l"(r) : "l"(a), "l"(b)); return r;
}
__device__ __forceinline__ float sqrta(float x) {
    float r; asm("sqrt.approx.f32 %0, %1;" : "=f"(r) : "f"(x)); return r;
}
__device__ __forceinline__ float rsqrta(float x) {
    float r; asm("rsqrt.approx.f32 %0, %1;" : "=f"(r) : "f"(x)); return r;
}

// acos on [0,1]: deg-7 minimax, abs err ~2e-8 (validated rel_err 0.0)
__device__ __forceinline__ float acos_fast(float x) {
    float p = fmaf(x, -0.0012624911f, 0.0066700901f);
    p = fmaf(x, p, -0.0170881256f);
    p = fmaf(x, p,  0.0308918810f);
    p = fmaf(x, p, -0.0501743046f);
    p = fmaf(x, p,  0.0889789874f);
    p = fmaf(x, p, -0.2145988016f);
    p = fmaf(x, p,  1.5707963050f);
    return sqrta(1.0f - x) * p;
}

// one pixel's gradient-magnitude L1 contribution (raw, unnormalized quats)
__device__ __forceinline__ float grad_term(float pc, float pr, float pd,
                                           float tc, float tr, float td) {
    float gxp = pr - pc, gyp = pd - pc;
    float gxt = tr - tc, gyt = td - tc;
    float gp = sqrta(fmaf(gxp, gxp, fmaf(gyp, gyp, EPSF)));
    float gt = sqrta(fmaf(gxt, gxt, fmaf(gyt, gyt, EPSF)));
    return fabsf(gp - gt);
}

__global__ __launch_bounds__(256, 4) void fused_loss_kernel(
    const float* __restrict__ qp,
    const float* __restrict__ qt,
    const float* __restrict__ syms,
    float* __restrict__ out)
{
    // Sign-adjusted symmetry splats, packed 2-wide
    __shared__ ulonglong2 s2[SS][2];
    __shared__ float2 wsum[8];
    __shared__ unsigned int curq_sh;
    __shared__ bool amLast;

    const int tid = threadIdx.x;
    if (tid < SS) {
        float a =  syms[tid * 4 + 0];
        float bv = -syms[tid * 4 + 1];
        float c = -syms[tid * 4 + 2];
        float d = -syms[tid * 4 + 3];
        s2[tid][0] = make_ulonglong2(pack2(a, a), pack2(bv, bv));
        s2[tid][1] = make_ulonglong2(pack2(c, c), pack2(d, d));
    }

    const ull NEG1 = pack2(-1.0f, -1.0f);
    const int t    = tid & 63;         // thread-in-row (64 per row)
    const int sub  = tid >> 6;         // row slot 0..3
    const int lane = tid & 31;
    const int warp = tid >> 5;
    const bool hasr = (t < 63);

    // ---- persistent work-stealing loop over row-quads ----
    // Partials are keyed by quad id, so the final fixed-order sum is
    // bitwise deterministic regardless of which block processes which quad.
    while (true) {
        if (tid == 0) curq_sh = atomicAdd(&g_work, 1u);
        __syncthreads();
        const unsigned int q = curq_sh;
        if (q >= NQUAD) break;

        const int row = (int)(q << 2) + sub;     // row = b*HH + h
        const int b   = row >> 8;
        const int h   = row & (HH - 1);
        const int base = b * 4 * PS + h * WW + (t << 2);
        const int dh  = (h < HH - 1) ? WW : -WW;  // mirrored edge (|diff| equal)

        // ---- per-channel: load + scalar gradient term ----
        float4 P[4], T[4];
        float gsum = 0.0f;
#pragma unroll
        for (int c = 0; c < 4; c++) {
            const float* pp = qp + base + c * PS;
            const float* tt = qt + base + c * PS;
            float4 p  = __ldg((const float4*)pp);
            float4 tq = __ldg((const float4*)tt);
            float4 pd = __ldg((const float4*)(pp + dh));
            float4 td = __ldg((const float4*)(tt + dh));
            float pr3 = hasr ? __ldg(pp + 4) : p.z;   // mirrored right edge
            float tr3 = hasr ? __ldg(tt + 4) : tq.z;

            gsum += grad_term(p.x, p.y, pd.x, tq.x, tq.y, td.x);
            gsum += grad_term(p.y, p.z, pd.y, tq.y, tq.z, td.y);
            gsum += grad_term(p.z, p.w, pd.z, tq.z, tq.w, td.z);
            gsum += grad_term(p.w, pr3, pd.w, tq.w, tr3, td.w);

            P[c] = p; T[c] = tq;
        }

        // ---- relative quaternion on RAW quats (normalization folded out) ----
        // r(p,t) is bilinear: r(p/|p|, t/|t|) = r(p,t) * (1/|p|)(1/|t|).
        ull RW[2], RX[2], RY[2], RZ[2];
        float s[4];
#pragma unroll
        for (int j = 0; j < 2; j++) {
            ull A0 = pack2(((const float*)&P[0])[2*j], ((const float*)&P[0])[2*j+1]);
            ull A1 = pack2(((const float*)&P[1])[2*j], ((const float*)&P[1])[2*j+1]);
            ull A2 = pack2(((const float*)&P[2])[2*j], ((const float*)&P[2])[2*j+1]);
            ull A3 = pack2(((const float*)&P[3])[2*j], ((const float*)&P[3])[2*j+1]);
            ull B0 = pack2(((const float*)&T[0])[2*j], ((const float*)&T[0])[2*j+1]);
            ull B1 = pack2(((const float*)&T[1])[2*j], ((const float*)&T[1])[2*j+1]);
            ull B2 = pack2(((const float*)&T[2])[2*j], ((const float*)&T[2])[2*j+1]);
            ull B3 = pack2(((const float*)&T[3])[2*j], ((const float*)&T[3])[2*j+1]);

            ull dp = fma2(A0, A0, fma2(A1, A1, fma2(A2, A2, mul2(A3, A3))));
            ull dt = fma2(B0, B0, fma2(B1, B1, fma2(B2, B2, mul2(B3, B3))));
            float dp0, dp1, dt0, dt1;
            unpack2(dp, dp0, dp1); unpack2(dt, dt0, dt1);
            s[2*j]   = rsqrta(dp0) * rsqrta(dt0);
            s[2*j+1] = rsqrta(dp1) * rsqrta(dt1);

            ull B0n = mul2(B0, NEG1);
            ull B1n = mul2(B1, NEG1);
            ull B2n = mul2(B2, NEG1);
            ull B3n = mul2(B3, NEG1);

            RW[j] = fma2(B0,  A0, fma2(B1,  A1, fma2(B2,  A2, mul2(B3,  A3))));
            RX[j] = fma2(B0n, A1, fma2(B1,  A0, fma2(B2n, A3, mul2(B3,  A2))));
            RY[j] = fma2(B0n, A2, fma2(B1,  A3, fma2(B2,  A0, mul2(B3n, A1))));
            RZ[j] = fma2(B0n, A3, fma2(B1n, A2, fma2(B2,  A1, mul2(B3,  A0))));
        }

        // ---- 24-symmetry max|dot|, packed; |x| folds into FMNMX ----
        float m0 = 0.0f, m1 = 0.0f, m2 = 0.0f, m3 = 0.0f;
#pragma unroll
        for (int sy = 0; sy < SS; sy++) {
            ulonglong2 vab = s2[sy][0];   // {x,x}, {y,y}
            ulonglong2 vcd = s2[sy][1];   // {z,z}, {w,w}
            ull d01 = fma2(RW[0], vab.x, fma2(RX[0], vab.y, fma2(RY[0], vcd.x, mul2(RZ[0], vcd.y))));
            ull d23 = fma2(RW[1], vab.x, fma2(RX[1], vab.y, fma2(RY[1], vcd.x, mul2(RZ[1], vcd.y))));
            float a, bb;
            unpack2(d01, a, bb); m0 = fmaxf(m0, fabsf(a)); m1 = fmaxf(m1, fabsf(bb));
            unpack2(d23, a, bb); m2 = fmaxf(m2, fabsf(a)); m3 = fmaxf(m3, fabsf(bb));
        }
        const float CL = 1.0f - EPSF;
        float rot = acos_fast(fminf(m0 * s[0], CL)) + acos_fast(fminf(m1 * s[1], CL))
                  + acos_fast(fminf(m2 * s[2], CL)) + acos_fast(fminf(m3 * s[3], CL));
        rot *= 2.0f;

        // ---- per-quad block reduction into g_partials[q] ----
        float r = rot, g = gsum;
#pragma unroll
        for (int o = 16; o > 0; o >>= 1) {
            r += __shfl_xor_sync(0xFFFFFFFFu, r, o);
            g += __shfl_xor_sync(0xFFFFFFFFu, g, o);
        }
        if (lane == 0) wsum[warp] = make_float2(r, g);
        __syncthreads();
        if (warp == 0) {
            float2 v = (lane < 8) ? wsum[lane] : make_float2(0.0f, 0.0f);
            float rr = v.x, gg = v.y;
#pragma unroll
            for (int o = 4; o > 0; o >>= 1) {
                rr += __shfl_xor_sync(0xFFFFFFFFu, rr, o);
                gg += __shfl_xor_sync(0xFFFFFFFFu, gg, o);
            }
            if (lane == 0) g_partials[q] = make_float2(rr, gg);
        }
        __syncthreads();   // wsum/curq_sh safe for next iteration
    }

    // ---- block done; last block performs the deterministic finish ----
    if (tid == 0) {
        __threadfence();
        unsigned int d = atomicAdd(&g_done, 1u);
        amLast = (d == GRID - 1);
    }
    __syncthreads();

    if (amLast) {
        float r2 = 0.0f, g2 = 0.0f;
#pragma unroll
        for (int i = tid; i < NQUAD; i += 256) {
            float2 v = __ldcg(&g_partials[i]);
            r2 += v.x; g2 += v.y;
        }
#pragma unroll
        for (int o = 16; o > 0; o >>= 1) {
            r2 += __shfl_xor_sync(0xFFFFFFFFu, r2, o);
            g2 += __shfl_xor_sync(0xFFFFFFFFu, g2, o);
        }
        if (lane == 0) wsum[warp] = make_float2(r2, g2);
        __syncthreads();
        if (tid == 0) {
            float rr = 0.0f, gg = 0.0f;
#pragma unroll
            for (int i = 0; i < 8; i++) { rr += wsum[i].x; gg += wsum[i].y; }
            out[0] = rr / (float)NPIX + WGRAD * (gg / (float)(4 * NPIX));
            g_work = 0;   // reset for next graph replay
            g_done = 0;
        }
    }
}

extern "C" void kernel_launch(void* const* d_in, const int* in_sizes, int n_in,
                              void* d_out, int out_size)
{
    const float* qp   = (const float*)d_in[0];
    const float* qt   = (const float*)d_in[1];
    const float* syms = (const float*)d_in[2];
    float* out = (float*)d_out;

    fused_loss_kernel<<<GRID, 256>>>(qp, qt, syms, out);
}

// round 9
// speedup vs baseline: 1.2393x; 1.2393x over previous
#include <cuda_runtime.h>
#include <math.h>
#include <stdint.h>

// Fixed problem shapes
#define BB 16
#define HH 256
#define WW 256
#define SS 24
#define PS (HH * WW)             // per-channel plane stride
#define NPIX (BB * HH * WW)      // 1,048,576
#define NQUAD 1024               // 4-row work units
#define GRID 296                 // 2 CTAs/SM on 148+ SMs, single wave
#define EPSF 1e-6f
#define WGRAD 0.05f

// SMEM staging: stage stride = 2 tensors * 4 ch * 5 rows * 256 floats
#define ROWF 256
#define CHROWS 5
#define CH_STRIDE (CHROWS * ROWF)            // floats per (tensor,ch)
#define STAGE_FLOATS (2 * 4 * CH_STRIDE)     // 10240 floats = 40KB
#define SMEM_BYTES (2 * STAGE_FLOATS * 4)    // 80KB double buffer

typedef unsigned long long ull;

__device__ float2 g_partials[GRID];
__device__ unsigned int g_count = 0;

// ---------- packed f32x2 + MUFU helpers ----------
__device__ __forceinline__ ull pack2(float lo, float hi) {
    ull r; asm("mov.b64 %0, {%1, %2};" : "=l"(r) : "f"(lo), "f"(hi)); return r;
}
__device__ __forceinline__ void unpack2(ull v, float& lo, float& hi) {
    asm("mov.b64 {%0, %1}, %2;" : "=f"(lo), "=f"(hi) : "l"(v));
}
__device__ __forceinline__ ull fma2(ull a, ull b, ull c) {
    ull r; asm("fma.rn.f32x2 %0, %1, %2, %3;" : "=l"(r) : "l"(a), "l"(b), "l"(c)); return r;
}
__device__ __forceinline__ ull mul2(ull a, ull b) {
    ull r; asm("mul.rn.f32x2 %0, %1, %2;" : "=l"(r) : "l"(a), "l"(b)); return r;
}
__device__ __forceinline__ float sqrta(float x) {
    float r; asm("sqrt.approx.f32 %0, %1;" : "=f"(r) : "f"(x)); return r;
}
__device__ __forceinline__ float rsqrta(float x) {
    float r; asm("rsqrt.approx.f32 %0, %1;" : "=f"(r) : "f"(x)); return r;
}

// acos on [0,1]: deg-7 minimax, abs err ~2e-8 (validated rel_err 0.0)
__device__ __forceinline__ float acos_fast(float x) {
    float p = fmaf(x, -0.0012624911f, 0.0066700901f);
    p = fmaf(x, p, -0.0170881256f);
    p = fmaf(x, p,  0.0308918810f);
    p = fmaf(x, p, -0.0501743046f);
    p = fmaf(x, p,  0.0889789874f);
    p = fmaf(x, p, -0.2145988016f);
    p = fmaf(x, p,  1.5707963050f);
    return sqrta(1.0f - x) * p;
}

// one pixel's gradient-magnitude L1 contribution (raw, unnormalized quats)
__device__ __forceinline__ float grad_term(float pc, float pr, float pd,
                                           float tc, float tr, float td) {
    float gxp = pr - pc, gyp = pd - pc;
    float gxt = tr - tc, gyt = td - tc;
    float gp = sqrta(fmaf(gxp, gxp, fmaf(gyp, gyp, EPSF)));
    float gt = sqrta(fmaf(gxt, gxt, fmaf(gyt, gyt, EPSF)));
    return fabsf(gp - gt);
}

__device__ __forceinline__ uint32_t smem_u32(const void* p) {
    uint32_t a;
    asm("{ .reg .u64 t; cvta.to.shared.u64 t, %1; cvt.u32.u64 %0, t; }"
        : "=r"(a) : "l"(p));
    return a;
}
__device__ __forceinline__ void mbar_init(uint32_t mbar, uint32_t cnt) {
    asm volatile("mbarrier.init.shared.b64 [%0], %1;" :: "r"(mbar), "r"(cnt) : "memory");
}
__device__ __forceinline__ void mbar_expect_tx(uint32_t mbar, uint32_t bytes) {
    asm volatile("mbarrier.arrive.expect_tx.shared.b64 _, [%0], %1;"
                 :: "r"(mbar), "r"(bytes) : "memory");
}
__device__ __forceinline__ void bulk_copy(uint32_t dst, const void* src,
                                          uint32_t bytes, uint32_t mbar) {
    asm volatile(
        "cp.async.bulk.shared::cta.global.mbarrier::complete_tx::bytes [%0], [%1], %2, [%3];"
        :: "r"(dst), "l"(src), "r"(bytes), "r"(mbar) : "memory");
}
__device__ __forceinline__ void mbar_wait(uint32_t mbar, uint32_t parity) {
    asm volatile(
        "{\n\t.reg .pred P;\n\t"
        "WL%=:\n\t"
        "mbarrier.try_wait.parity.acquire.cta.shared::cta.b64 P, [%0], %1, 0x989680;\n\t"
        "@!P bra WL%=;\n\t}"
        :: "r"(mbar), "r"(parity) : "memory");
}

// Issue the 8 bulk copies for quad q into stage s (caller: one thread).
__device__ __forceinline__ void issue_quad(uint32_t smem_base, int s,
                                           const float* qp, const float* qt,
                                           int q, uint32_t mbar) {
    const int row0 = q << 2;
    const int b    = row0 >> 8;
    const int h0   = row0 & (HH - 1);
    const int nrows = (h0 == HH - 4) ? 4 : 5;          // avoid OOB at image bottom
    const uint32_t bytes = (uint32_t)nrows * (WW * 4);
    mbar_expect_tx(mbar, 8u * bytes);
#pragma unroll
    for (int tn = 0; tn < 2; tn++) {
        const float* src0 = (tn ? qt : qp) + ((b * 4) * HH + h0) * WW;
#pragma unroll
        for (int c = 0; c < 4; c++) {
            uint32_t dst = smem_base + (uint32_t)((s * STAGE_FLOATS +
                           (tn * 4 + c) * CH_STRIDE) * 4);
            bulk_copy(dst, src0 + c * (HH * WW), bytes, mbar);
        }
    }
}

__global__ __launch_bounds__(256, 2) void fused_loss_kernel(
    const float* __restrict__ qp,
    const float* __restrict__ qt,
    const float* __restrict__ syms,
    float* __restrict__ out)
{
    extern __shared__ float sbuf[];
    const uint32_t sbase = smem_u32(sbuf);

    __shared__ ulonglong2 s2[SS][2];
    __shared__ float2 wsum[8];
    __shared__ bool amLast;
    __shared__ ull mbar_store[2];

    const int tid = threadIdx.x;
    const uint32_t mbar0 = smem_u32(&mbar_store[0]);
    const uint32_t mbar1 = smem_u32(&mbar_store[1]);

    if (tid < SS) {
        float a =  syms[tid * 4 + 0];
        float bv = -syms[tid * 4 + 1];
        float c = -syms[tid * 4 + 2];
        float d = -syms[tid * 4 + 3];
        s2[tid][0] = make_ulonglong2(pack2(a, a), pack2(bv, bv));
        s2[tid][1] = make_ulonglong2(pack2(c, c), pack2(d, d));
    }
    if (tid == 0) {
        mbar_init(mbar0, 1);
        mbar_init(mbar1, 1);
    }
    __syncthreads();

    // Static deterministic block -> quad mapping: 136 blocks x4, 160 x3 = 1024
    int nq, q0;
    if (blockIdx.x < 136) { nq = 4; q0 = blockIdx.x * 4; }
    else                  { nq = 3; q0 = 544 + (blockIdx.x - 136) * 3; }

    if (tid == 0) issue_quad(sbase, 0, qp, qt, q0, mbar0);

    const ull NEG1 = pack2(-1.0f, -1.0f);
    const int t    = tid & 63;         // thread-in-row (64 per row)
    const int sub  = tid >> 6;         // row slot 0..3
    const int lane = tid & 31;
    const int warp = tid >> 5;
    const bool hasr = (t < 63);

    float racc = 0.0f, gacc = 0.0f;

#pragma unroll 1
    for (int k = 0; k < nq; k++) {
        const int s = k & 1;
        // prefetch next quad into the other stage (consumed 2 iters ago)
        if (tid == 0 && k + 1 < nq)
            issue_quad(sbase, (k + 1) & 1, qp, qt, q0 + k + 1, s ? mbar0 : mbar1);

        mbar_wait(s ? mbar1 : mbar0, (k >> 1) & 1);

        const int q   = q0 + k;
        const int h   = (q << 2 & (HH - 1)) + sub;   // global h of this row
        const int dr  = (h < HH - 1) ? sub + 1 : sub - 1;  // mirrored bottom edge
        const float* stg = sbuf + s * STAGE_FLOATS;

        // ---- per-channel: SMEM loads + scalar gradient term ----
        float4 P[4], T[4];
        float gsum = 0.0f;
#pragma unroll
        for (int c = 0; c < 4; c++) {
            const float* pc = stg + c * CH_STRIDE;
            const float* tc = stg + (4 + c) * CH_STRIDE;
            float4 p  = *(const float4*)(pc + sub * ROWF + (t << 2));
            float4 tq = *(const float4*)(tc + sub * ROWF + (t << 2));
            float4 pd = *(const float4*)(pc + dr  * ROWF + (t << 2));
            float4 td = *(const float4*)(tc + dr  * ROWF + (t << 2));
            float pr3 = hasr ? pc[sub * ROWF + (t << 2) + 4] : p.z;  // mirrored right edge
            float tr3 = hasr ? tc[sub * ROWF + (t << 2) + 4] : tq.z;

            gsum += grad_term(p.x, p.y, pd.x, tq.x, tq.y, td.x);
            gsum += grad_term(p.y, p.z, pd.y, tq.y, tq.z, td.y);
            gsum += grad_term(p.z, p.w, pd.z, tq.z, tq.w, td.z);
            gsum += grad_term(p.w, pr3, pd.w, tq.w, tr3, td.w);

            P[c] = p; T[c] = tq;
        }
        gacc += gsum;

        // ---- relative quaternion on RAW quats (normalization folded out) ----
        ull RW[2], RX[2], RY[2], RZ[2];
        float sc[4];
#pragma unroll
        for (int j = 0; j < 2; j++) {
            ull A0 = pack2(((const float*)&P[0])[2*j], ((const float*)&P[0])[2*j+1]);
            ull A1 = pack2(((const float*)&P[1])[2*j], ((const float*)&P[1])[2*j+1]);
            ull A2 = pack2(((const float*)&P[2])[2*j], ((const float*)&P[2])[2*j+1]);
            ull A3 = pack2(((const float*)&P[3])[2*j], ((const float*)&P[3])[2*j+1]);
            ull B0 = pack2(((const float*)&T[0])[2*j], ((const float*)&T[0])[2*j+1]);
            ull B1 = pack2(((const float*)&T[1])[2*j], ((const float*)&T[1])[2*j+1]);
            ull B2 = pack2(((const float*)&T[2])[2*j], ((const float*)&T[2])[2*j+1]);
            ull B3 = pack2(((const float*)&T[3])[2*j], ((const float*)&T[3])[2*j+1]);

            ull dp = fma2(A0, A0, fma2(A1, A1, fma2(A2, A2, mul2(A3, A3))));
            ull dt = fma2(B0, B0, fma2(B1, B1, fma2(B2, B2, mul2(B3, B3))));
            float dp0, dp1, dt0, dt1;
            unpack2(dp, dp0, dp1); unpack2(dt, dt0, dt1);
            sc[2*j]   = rsqrta(dp0) * rsqrta(dt0);
            sc[2*j+1] = rsqrta(dp1) * rsqrta(dt1);

            ull B0n = mul2(B0, NEG1);
            ull B1n = mul2(B1, NEG1);
            ull B2n = mul2(B2, NEG1);
            ull B3n = mul2(B3, NEG1);

            RW[j] = fma2(B0,  A0, fma2(B1,  A1, fma2(B2,  A2, mul2(B3,  A3))));
            RX[j] = fma2(B0n, A1, fma2(B1,  A0, fma2(B2n, A3, mul2(B3,  A2))));
            RY[j] = fma2(B0n, A2, fma2(B1,  A3, fma2(B2,  A0, mul2(B3n, A1))));
            RZ[j] = fma2(B0n, A3, fma2(B1n, A2, fma2(B2,  A1, mul2(B3,  A0))));
        }

        // ---- 24-symmetry max|dot|, packed ----
        float m0 = 0.0f, m1 = 0.0f, m2 = 0.0f, m3 = 0.0f;
#pragma unroll
        for (int sy = 0; sy < SS; sy++) {
            ulonglong2 vab = s2[sy][0];
            ulonglong2 vcd = s2[sy][1];
            ull d01 = fma2(RW[0], vab.x, fma2(RX[0], vab.y, fma2(RY[0], vcd.x, mul2(RZ[0], vcd.y))));
            ull d23 = fma2(RW[1], vab.x, fma2(RX[1], vab.y, fma2(RY[1], vcd.x, mul2(RZ[1], vcd.y))));
            float a, bb;
            unpack2(d01, a, bb); m0 = fmaxf(m0, fabsf(a)); m1 = fmaxf(m1, fabsf(bb));
            unpack2(d23, a, bb); m2 = fmaxf(m2, fabsf(a)); m3 = fmaxf(m3, fabsf(bb));
        }
        const float CL = 1.0f - EPSF;
        racc += acos_fast(fminf(m0 * sc[0], CL)) + acos_fast(fminf(m1 * sc[1], CL))
              + acos_fast(fminf(m2 * sc[2], CL)) + acos_fast(fminf(m3 * sc[3], CL));

        __syncthreads();   // stage s free for reuse at iteration k+2
    }

    float rot = racc * 2.0f;

    // ---- block reduction ----
    float r = rot, g = gacc;
#pragma unroll
    for (int o = 16; o > 0; o >>= 1) {
        r += __shfl_xor_sync(0xFFFFFFFFu, r, o);
        g += __shfl_xor_sync(0xFFFFFFFFu, g, o);
    }
    if (lane == 0) wsum[warp] = make_float2(r, g);
    __syncthreads();
    if (warp == 0) {
        float2 v = (lane < 8) ? wsum[lane] : make_float2(0.0f, 0.0f);
        float rr = v.x, gg = v.y;
#pragma unroll
        for (int o = 4; o > 0; o >>= 1) {
            rr += __shfl_xor_sync(0xFFFFFFFFu, rr, o);
            gg += __shfl_xor_sync(0xFFFFFFFFu, gg, o);
        }
        if (lane == 0) {
            g_partials[blockIdx.x] = make_float2(rr, gg);
            __threadfence();
            unsigned int c = atomicAdd(&g_count, 1u);
            amLast = (c == GRID - 1);
        }
    }
    __syncthreads();

    // ---- last block: grid-wide finish (deterministic fixed-order sum) ----
    if (amLast) {
        float r2 = 0.0f, g2 = 0.0f;
        for (int i = tid; i < GRID; i += 256) {
            float2 v = __ldcg(&g_partials[i]);
            r2 += v.x; g2 += v.y;
        }
#pragma unroll
        for (int o = 16; o > 0; o >>= 1) {
            r2 += __shfl_xor_sync(0xFFFFFFFFu, r2, o);
            g2 += __shfl_xor_sync(0xFFFFFFFFu, g2, o);
        }
        if (lane == 0) wsum[warp] = make_float2(r2, g2);
        __syncthreads();
        if (tid == 0) {
            float rr = 0.0f, gg = 0.0f;
#pragma unroll
            for (int i = 0; i < 8; i++) { rr += wsum[i].x; gg += wsum[i].y; }
            out[0] = rr / (float)NPIX + WGRAD * (gg / (float)(4 * NPIX));
            g_count = 0;   // reset for next graph replay
        }
    }
}

extern "C" void kernel_launch(void* const* d_in, const int* in_sizes, int n_in,
                              void* d_out, int out_size)
{
    const float* qp   = (const float*)d_in[0];
    const float* qt   = (const float*)d_in[1];
    const float* syms = (const float*)d_in[2];
    float* out = (float*)d_out;

    cudaFuncSetAttribute(fused_loss_kernel,
                         cudaFuncAttributeMaxDynamicSharedMemorySize, SMEM_BYTES);
    fused_loss_kernel<<<GRID, 256, SMEM_BYTES>>>(qp, qt, syms, out);
}